// round 6
// baseline (speedup 1.0000x reference)
#include <cuda_runtime.h>
#include <cuda_bf16.h>
#include <cstdint>

#define B_  4
#define NXq 1024
#define NYk 1024
#define C_  768
#define H_  12
#define D_  64

// ======================= scratch (static device globals) =======================
__device__ __align__(16) __nv_bfloat16 g_x16 [B_*NXq*C_];
__device__ __align__(16) __nv_bfloat16 g_yn16[B_*NYk*C_];
__device__ __align__(16) __nv_bfloat16 g_q16 [B_*NXq*C_];
__device__ __align__(16) __nv_bfloat16 g_kv16[B_*NYk*2*C_];
__device__ __align__(16) __nv_bfloat16 g_vt16[48*64*1024];
__device__ __align__(16) __nv_bfloat16 g_W   [48u*1024u*1024u];
__device__ __align__(16) __nv_bfloat16 g_at16[B_*NXq*C_];
__device__ __align__(16) __nv_bfloat16 g_qw16 [C_*C_];
__device__ __align__(16) __nv_bfloat16 g_kvw16[2*C_*C_];
__device__ __align__(16) __nv_bfloat16 g_pw16 [C_*C_];

__device__ __forceinline__ uint32_t smem_u32(const void* p) {
    uint32_t a;
    asm("{ .reg .u64 t; cvta.to.shared.u64 t, %1; cvt.u32.u64 %0, t; }" : "=r"(a) : "l"(p));
    return a;
}
__device__ __forceinline__ void cp16(uint32_t dst, const void* src) {
    asm volatile("cp.async.cg.shared.global [%0], [%1], 16;" :: "r"(dst), "l"(src));
}

// ======================= fused multiscale conv + LayerNorm -> bf16 =======================
__global__ void __launch_bounds__(256) conv_ln_kernel(
    const float* __restrict__ y,
    const float* __restrict__ c1w, const float* __restrict__ c1b,
    const float* __restrict__ c2w, const float* __restrict__ c2b,
    const float* __restrict__ c3w, const float* __restrict__ c3b,
    const float* __restrict__ lnw, const float* __restrict__ lnb)
{
    int row = blockIdx.x;
    int b  = row >> 10;
    int ny = row & 1023;
    const float* yb = y + (size_t)b * NYk * C_;
    int tid = threadIdx.x;

    float vals[3];
    float lsum = 0.f, lsq = 0.f;
    #pragma unroll
    for (int i = 0; i < 3; i++) {
        int c = tid + i * 256;
        float w7[7];
        #pragma unroll
        for (int j = 0; j < 7; j++) w7[j] = c3w[c*7 + j];
        #pragma unroll
        for (int j = 0; j < 5; j++) w7[j+1] += c2w[c*5 + j];
        #pragma unroll
        for (int j = 0; j < 3; j++) w7[j+2] += c1w[c*3 + j];
        float acc = c1b[c] + c2b[c] + c3b[c];
        #pragma unroll
        for (int j = 0; j < 7; j++) {
            int nn = ny + j - 3;
            if (nn >= 0 && nn < NYk) acc += w7[j] * yb[(size_t)nn * C_ + c];
        }
        vals[i] = acc; lsum += acc; lsq += acc * acc;
    }

    __shared__ float s1[256], s2[256];
    s1[tid] = lsum; s2[tid] = lsq;
    __syncthreads();
    for (int s = 128; s > 0; s >>= 1) {
        if (tid < s) { s1[tid] += s1[tid+s]; s2[tid] += s2[tid+s]; }
        __syncthreads();
    }
    float mean = s1[0] * (1.0f / C_);
    float var  = s2[0] * (1.0f / C_) - mean * mean;
    float rstd = rsqrtf(var + 1e-5f);

    size_t base = (size_t)row * C_;
    #pragma unroll
    for (int i = 0; i < 3; i++) {
        int c = tid + i * 256;
        float v = (vals[i] - mean) * rstd * lnw[c] + lnb[c];
        g_yn16[base + c] = __float2bfloat16(v);
    }
}

// ======================= fp32 -> bf16 convert =======================
__global__ void __launch_bounds__(256) cvt_kernel(const float* __restrict__ s,
                                                  __nv_bfloat16* __restrict__ o,
                                                  int n4)
{
    int i = blockIdx.x * 256 + threadIdx.x;
    if (i >= n4) return;
    float4 v = ((const float4*)s)[i];
    __nv_bfloat162* O = (__nv_bfloat162*)o;
    O[2*i]   = __halves2bfloat162(__float2bfloat16(v.x), __float2bfloat16(v.y));
    O[2*i+1] = __halves2bfloat162(__float2bfloat16(v.z), __float2bfloat16(v.w));
}

// ======================= V transpose =======================
__global__ void __launch_bounds__(256) vtrans_kernel()
{
    int z  = blockIdx.x;
    int t0 = blockIdx.y * 32;
    int b = z / 12, h = z - b*12;
    __shared__ __nv_bfloat16 sh[64][33];
    int tid = threadIdx.x;
    #pragma unroll
    for (int i = 0; i < 8; i++) {
        int idx = tid + i*256;
        int tok = idx >> 6, d = idx & 63;
        size_t off = ((size_t)(b*1024 + t0 + tok)) * 1536 + 768 + h*64 + d;
        sh[d][tok] = g_kv16[off];
    }
    __syncthreads();
    #pragma unroll
    for (int i = 0; i < 8; i++) {
        int o = tid + i*256;
        int d = o >> 5, c = o & 31;
        size_t off = (size_t)z * 64 * 1024 + (size_t)d * 1024 + t0 + c;
        g_vt16[off] = sh[d][c];
    }
}

// ======================= HMMA GEMM (unchanged from R5) =======================
template<int NT, int OUTM>
__global__ void __launch_bounds__(256) mma_gemm(
    const __nv_bfloat16* __restrict__ A, const __nv_bfloat16* __restrict__ B,
    float* __restrict__ Co, __nv_bfloat16* __restrict__ Cb,
    const float* __restrict__ bias, const float* __restrict__ res,
    int K, int lda, int ldb, int ldc, float alpha, int HH,
    long long aO, long long aI, long long bO, long long bI,
    long long cO, long long cI)
{
    constexpr int WM  = (NT == 128) ? 2 : 4;
    constexpr int WN  = 8 / WM;
    constexpr int WTM = 128 / WM;
    constexpr int WTN = NT / WN;
    constexpr int MT  = WTM / 16;
    constexpr int NTT = WTN / 8;
    constexpr int PITCH = 72;
    constexpr int ABYTES = 128 * PITCH * 2;
    constexpr int BBYTES = NT  * PITCH * 2;
    constexpr int STAGE  = ABYTES + BBYTES;

    extern __shared__ __align__(16) char dsm[];
    uint32_t smbase = smem_u32(dsm);

    int tid = threadIdx.x, wid = tid >> 5, lane = tid & 31;
    int wm = wid % WM, wn = wid / WM;

    int z = blockIdx.z, zo = z / HH, zi = z - zo * HH;
    A += zo*aO + zi*aI;
    B += zo*bO + zi*bI;
    long long coff = zo*cO + zi*cI;

    long long m0 = (long long)blockIdx.y * 128;
    long long n0 = (long long)blockIdx.x * NT;

    float acc[MT][NTT][4];
    #pragma unroll
    for (int i = 0; i < MT; i++)
        #pragma unroll
        for (int j = 0; j < NTT; j++)
            #pragma unroll
            for (int r = 0; r < 4; r++) acc[i][j][r] = 0.f;

    int nIter = K >> 6;

    uint32_t a_off = ((uint32_t)(wm*WTM + (lane & 15)) * PITCH + ((lane >> 4) << 3)) * 2;
    uint32_t b_off = ABYTES + ((uint32_t)(wn*WTN + (lane & 7)) * PITCH + (((lane >> 3) & 1) << 3)) * 2;

    auto issue = [&](int t) {
        int k0 = t << 6, s = t & 1;
        uint32_t sa = smbase + s * STAGE;
        uint32_t sb = sa + ABYTES;
        #pragma unroll
        for (int i = 0; i < 4; i++) {
            int ch = tid + (i << 8);
            int r = ch >> 3, c = (ch & 7) << 3;
            cp16(sa + (uint32_t)(r*PITCH + c)*2, A + (m0 + r)*lda + k0 + c);
        }
        #pragma unroll
        for (int i = 0; i < NT/32; i++) {
            int ch = tid + (i << 8);
            int r = ch >> 3, c = (ch & 7) << 3;
            cp16(sb + (uint32_t)(r*PITCH + c)*2, B + (n0 + r)*ldb + k0 + c);
        }
        asm volatile("cp.async.commit_group;");
    };

    issue(0);
    for (int t = 0; t < nIter; t++) {
        if (t + 1 < nIter) {
            issue(t + 1);
            asm volatile("cp.async.wait_group 1;");
        } else {
            asm volatile("cp.async.wait_group 0;");
        }
        __syncthreads();
        uint32_t stg = smbase + (uint32_t)(t & 1) * STAGE;
        uint32_t abase = stg + a_off;
        uint32_t bbase = stg + b_off;

        #pragma unroll
        for (int ks = 0; ks < 4; ks++) {
            uint32_t kb = (uint32_t)ks << 5;
            uint32_t af[MT][4];
            #pragma unroll
            for (int mt = 0; mt < MT; mt++) {
                asm volatile("ldmatrix.sync.aligned.m8n8.x4.shared.b16 {%0,%1,%2,%3}, [%4];"
                    : "=r"(af[mt][0]), "=r"(af[mt][1]), "=r"(af[mt][2]), "=r"(af[mt][3])
                    : "r"(abase + (uint32_t)(mt*16*PITCH*2) + kb));
            }
            uint32_t bf[NTT][2];
            #pragma unroll
            for (int nt = 0; nt < NTT; nt++) {
                asm volatile("ldmatrix.sync.aligned.m8n8.x2.shared.b16 {%0,%1}, [%2];"
                    : "=r"(bf[nt][0]), "=r"(bf[nt][1])
                    : "r"(bbase + (uint32_t)(nt*8*PITCH*2) + kb));
            }
            #pragma unroll
            for (int mt = 0; mt < MT; mt++)
                #pragma unroll
                for (int nt = 0; nt < NTT; nt++) {
                    asm volatile(
                        "mma.sync.aligned.m16n8k16.row.col.f32.bf16.bf16.f32 "
                        "{%0,%1,%2,%3}, {%4,%5,%6,%7}, {%8,%9}, {%0,%1,%2,%3};"
                        : "+f"(acc[mt][nt][0]), "+f"(acc[mt][nt][1]),
                          "+f"(acc[mt][nt][2]), "+f"(acc[mt][nt][3])
                        : "r"(af[mt][0]), "r"(af[mt][1]), "r"(af[mt][2]), "r"(af[mt][3]),
                          "r"(bf[nt][0]), "r"(bf[nt][1]));
                }
        }
        __syncthreads();
    }

    int gg = lane >> 2, qq = lane & 3;
    #pragma unroll
    for (int mt = 0; mt < MT; mt++) {
        long long gm = m0 + wm*WTM + mt*16 + gg;
        #pragma unroll
        for (int nt = 0; nt < NTT; nt++) {
            long long gn = n0 + wn*WTN + nt*8 + 2*qq;
            float v0 = acc[mt][nt][0] * alpha;
            float v1 = acc[mt][nt][1] * alpha;
            float v2 = acc[mt][nt][2] * alpha;
            float v3 = acc[mt][nt][3] * alpha;
            long long gi0 = coff + gm * (long long)ldc + gn;
            long long gi1 = gi0 + 8LL * ldc;
            if (OUTM == 0) {
                *(float2*)&Co[gi0] = make_float2(v0, v1);
                *(float2*)&Co[gi1] = make_float2(v2, v3);
            } else if (OUTM == 1) {
                float b0 = bias[gn], b1 = bias[gn + 1];
                float2 r0 = *(const float2*)&res[gi0];
                float2 r1 = *(const float2*)&res[gi1];
                *(float2*)&Co[gi0] = make_float2(v0 + b0 + r0.x, v1 + b1 + r0.y);
                *(float2*)&Co[gi1] = make_float2(v2 + b0 + r1.x, v3 + b1 + r1.y);
            } else {
                *(__nv_bfloat162*)&Cb[gi0] =
                    __halves2bfloat162(__float2bfloat16(v0), __float2bfloat16(v1));
                *(__nv_bfloat162*)&Cb[gi1] =
                    __halves2bfloat162(__float2bfloat16(v2), __float2bfloat16(v3));
            }
        }
    }
}

// ======================= FUSED: score GEMM + dual top-k + softmax weights =======================
// Grid: (32 m-tiles, 48 heads). CTA computes 32x1024 scores in HMMA accumulators,
// radix-selects both thresholds from registers via 32-row shared histograms,
// writes combined softmax weights W (bf16) to HBM. No S matrix in HBM.
#define HP 272   // hist row pitch (words), padded vs 256 to rotate banks across rows

__global__ void __launch_bounds__(256, 1) score_select_kernel(
    const int* __restrict__ pk1, const int* __restrict__ pk2)
{
    extern __shared__ __align__(16) char dsm[];
    uint32_t smb = smem_u32(dsm);
    unsigned* hist = (unsigned*)dsm;             // [2][32][HP] reuses GEMM staging

    __shared__ unsigned s_umax[32];
    __shared__ unsigned upart[32][8];
    __shared__ unsigned s_p[2][32];
    __shared__ int      s_kk[2][32];
    __shared__ float    zp[2][32][8];
    __shared__ float    s_z[2][32];

    constexpr int PITCH = 72;
    constexpr uint32_t A_OFF = 0;                // 32*72*2   = 4608 B
    constexpr uint32_t B_OFF = 4608;             // 2 x 128*72*2 = 36864 B
    constexpr uint32_t BSTG  = 128 * PITCH * 2;

    int tid = threadIdx.x, w = tid >> 5, lane = tid & 31;
    int gg = lane >> 2, qq = lane & 3;
    int head = blockIdx.y;
    int b = head / 12, h = head - b*12;
    int m0 = blockIdx.x * 32;

    const __nv_bfloat16* Aq = g_q16  + (size_t)(b*1024 + m0) * 768 + h*64;
    const __nv_bfloat16* Kb = g_kv16 + (size_t)(b*1024) * 1536 + h*64;

    int k1 = *pk1, k2 = *pk2;

    // ---------------- phase A: 32x1024 score GEMM, acc in regs ----------------
    float acc[8][2][2][4];
    #pragma unroll
    for (int c = 0; c < 8; c++)
        #pragma unroll
        for (int mt = 0; mt < 2; mt++)
            #pragma unroll
            for (int nt = 0; nt < 2; nt++)
                #pragma unroll
                for (int e = 0; e < 4; e++) acc[c][mt][nt][e] = 0.f;

    auto issueB = [&](int c) {
        uint32_t sb = smb + B_OFF + (uint32_t)(c & 1) * BSTG;
        const __nv_bfloat16* Bp = Kb + (size_t)(c * 128) * 1536;
        #pragma unroll
        for (int i = 0; i < 4; i++) {
            int ch = tid + (i << 8);
            int r = ch >> 3, col = (ch & 7) << 3;
            cp16(sb + (uint32_t)(r*PITCH + col)*2, Bp + (size_t)r*1536 + col);
        }
        asm volatile("cp.async.commit_group;");
    };

    {   // A tile (32x64) in group 0 along with B chunk 0
        int r = tid >> 3, col = (tid & 7) << 3;
        cp16(smb + A_OFF + (uint32_t)(r*PITCH + col)*2, Aq + (size_t)r*768 + col);
    }
    issueB(0);

    uint32_t a_off = A_OFF + ((uint32_t)(lane & 15) * PITCH + ((lane >> 4) << 3)) * 2;
    uint32_t b_off = ((uint32_t)((lane & 7) + w*16) * PITCH + (((lane >> 3) & 1) << 3)) * 2;

    uint32_t af[2][4][4];
    #pragma unroll
    for (int c = 0; c < 8; c++) {
        if (c < 7) {
            issueB(c + 1);
            asm volatile("cp.async.wait_group 1;");
        } else {
            asm volatile("cp.async.wait_group 0;");
        }
        __syncthreads();
        if (c == 0) {
            #pragma unroll
            for (int mt = 0; mt < 2; mt++)
                #pragma unroll
                for (int ks = 0; ks < 4; ks++) {
                    asm volatile("ldmatrix.sync.aligned.m8n8.x4.shared.b16 {%0,%1,%2,%3}, [%4];"
                        : "=r"(af[mt][ks][0]), "=r"(af[mt][ks][1]),
                          "=r"(af[mt][ks][2]), "=r"(af[mt][ks][3])
                        : "r"(smb + a_off + (uint32_t)(mt*16*PITCH*2) + ((uint32_t)ks << 5)));
                }
        }
        uint32_t bb = smb + B_OFF + (uint32_t)(c & 1) * BSTG + b_off;
        #pragma unroll
        for (int ks = 0; ks < 4; ks++) {
            uint32_t bf[2][2];
            #pragma unroll
            for (int nt = 0; nt < 2; nt++) {
                asm volatile("ldmatrix.sync.aligned.m8n8.x2.shared.b16 {%0,%1}, [%2];"
                    : "=r"(bf[nt][0]), "=r"(bf[nt][1])
                    : "r"(bb + (uint32_t)(nt*8*PITCH*2) + ((uint32_t)ks << 5)));
            }
            #pragma unroll
            for (int mt = 0; mt < 2; mt++)
                #pragma unroll
                for (int nt = 0; nt < 2; nt++) {
                    asm volatile(
                        "mma.sync.aligned.m16n8k16.row.col.f32.bf16.bf16.f32 "
                        "{%0,%1,%2,%3}, {%4,%5,%6,%7}, {%8,%9}, {%0,%1,%2,%3};"
                        : "+f"(acc[c][mt][nt][0]), "+f"(acc[c][mt][nt][1]),
                          "+f"(acc[c][mt][nt][2]), "+f"(acc[c][mt][nt][3])
                        : "r"(af[mt][ks][0]), "r"(af[mt][ks][1]),
                          "r"(af[mt][ks][2]), "r"(af[mt][ks][3]),
                          "r"(bf[nt][0]), "r"(bf[nt][1]));
                }
        }
        __syncthreads();
    }

    // scale + map to monotone uint key space (store keys in acc regs)
    #pragma unroll
    for (int c = 0; c < 8; c++)
        #pragma unroll
        for (int mt = 0; mt < 2; mt++)
            #pragma unroll
            for (int nt = 0; nt < 2; nt++)
                #pragma unroll
                for (int e = 0; e < 4; e++) {
                    float v = acc[c][mt][nt][e] * 0.125f;
                    unsigned bb2 = __float_as_uint(v);
                    unsigned u = (bb2 & 0x80000000u) ? ~bb2 : (bb2 | 0x80000000u);
                    acc[c][mt][nt][e] = __uint_as_float(u);
                }

    // ---------------- row max (u-space, deterministic) ----------------
    {
        unsigned um[4] = {0u, 0u, 0u, 0u};
        #pragma unroll
        for (int c = 0; c < 8; c++)
            #pragma unroll
            for (int mt = 0; mt < 2; mt++)
                #pragma unroll
                for (int nt = 0; nt < 2; nt++)
                    #pragma unroll
                    for (int e = 0; e < 4; e++) {
                        int rs = (e >> 1) + 2*mt;
                        unsigned u = __float_as_uint(acc[c][mt][nt][e]);
                        um[rs] = (u > um[rs]) ? u : um[rs];
                    }
        #pragma unroll
        for (int rs = 0; rs < 4; rs++) {
            unsigned v1 = __shfl_xor_sync(0xFFFFFFFFu, um[rs], 1);
            um[rs] = (v1 > um[rs]) ? v1 : um[rs];
            unsigned v2 = __shfl_xor_sync(0xFFFFFFFFu, um[rs], 2);
            um[rs] = (v2 > um[rs]) ? v2 : um[rs];
            if (qq == 0) upart[gg + 8*rs][w] = um[rs];
        }
    }
    __syncthreads();
    if (tid < 32) {
        unsigned m = upart[tid][0];
        #pragma unroll
        for (int j = 1; j < 8; j++) m = (upart[tid][j] > m) ? upart[tid][j] : m;
        s_umax[tid] = m;
        s_p[0][tid] = 0u; s_p[1][tid] = 0u;
        s_kk[0][tid] = k1; s_kk[1][tid] = k2;
    }

    // warp-scan of one row's 256-bin hist; updates (s_p, s_kk) for threshold t
    auto scan_update = [&](const unsigned* hrow, int t, int row, int sh) {
        int kk = s_kk[t][row];
        unsigned pfx = s_p[t][row];
        unsigned h8[8];
        #pragma unroll
        for (int i = 0; i < 8; i++) h8[i] = hrow[lane*8 + i];
        unsigned tot = 0;
        #pragma unroll
        for (int i = 0; i < 8; i++) tot += h8[i];
        unsigned s = tot;
        #pragma unroll
        for (int d = 1; d < 32; d <<= 1) {
            unsigned tt = __shfl_down_sync(0xFFFFFFFFu, s, d);
            if (lane + d < 32) s += tt;
        }
        unsigned run = s - tot;   // counts in bins above this lane's range
        #pragma unroll
        for (int i = 7; i >= 0; i--) {
            unsigned cn = run;
            run += h8[i];
            if (run >= (unsigned)kk && cn < (unsigned)kk) {
                s_p[t][row] = pfx | ((unsigned)(lane*8 + i) << sh);
                s_kk[t][row] = kk - (int)cn;
            }
        }
    };

    // ---------------- level 3 (top byte, unfiltered, shared hist) ----------------
    for (int i = tid; i < 32*HP; i += 256) hist[i] = 0u;
    __syncthreads();
    #pragma unroll
    for (int c = 0; c < 8; c++)
        #pragma unroll
        for (int mt = 0; mt < 2; mt++)
            #pragma unroll
            for (int nt = 0; nt < 2; nt++)
                #pragma unroll
                for (int e = 0; e < 4; e++) {
                    int row = gg + 8*(e >> 1) + 16*mt;
                    unsigned u = __float_as_uint(acc[c][mt][nt][e]);
                    unsigned key = ((unsigned)row << 8) | (u >> 24);
                    unsigned mm = __match_any_sync(0xFFFFFFFFu, key);
                    if ((int)lane == __ffs(mm) - 1)
                        atomicAdd(&hist[row*HP + (u >> 24)], __popc(mm));
                }
    __syncthreads();
    #pragma unroll
    for (int j = 0; j < 4; j++) {
        int row = w + 8*j;
        scan_update(&hist[row*HP], 0, row, 24);
        scan_update(&hist[row*HP], 1, row, 24);
    }
    __syncthreads();

    // ---------------- levels 2..0 ----------------
    #pragma unroll
    for (int lev = 2; lev >= 0; lev--) {
        int sh = lev * 8;
        unsigned himask = 0xFFFFFFFFu << (sh + 8);
        unsigned p1r[4], p2r[4];
        #pragma unroll
        for (int rs = 0; rs < 4; rs++) {
            p1r[rs] = s_p[0][gg + 8*rs];
            p2r[rs] = s_p[1][gg + 8*rs];
        }
        __syncthreads();
        for (int i = tid; i < 2*32*HP; i += 256) hist[i] = 0u;
        __syncthreads();
        #pragma unroll
        for (int c = 0; c < 8; c++)
            #pragma unroll
            for (int mt = 0; mt < 2; mt++)
                #pragma unroll
                for (int nt = 0; nt < 2; nt++)
                    #pragma unroll
                    for (int e = 0; e < 4; e++) {
                        int rs = (e >> 1) + 2*mt;
                        int row = gg + 8*rs;
                        unsigned u = __float_as_uint(acc[c][mt][nt][e]);
                        if (((u ^ p1r[rs]) & himask) == 0u)
                            atomicAdd(&hist[row*HP + ((u >> sh) & 255u)], 1u);
                        if (p2r[rs] != p1r[rs] && ((u ^ p2r[rs]) & himask) == 0u)
                            atomicAdd(&hist[32*HP + row*HP + ((u >> sh) & 255u)], 1u);
                    }
        __syncthreads();
        #pragma unroll
        for (int j = 0; j < 4; j++) {
            int row = w + 8*j;
            bool same = (s_p[0][row] == s_p[1][row]);
            scan_update(&hist[row*HP], 0, row, sh);
            scan_update(same ? &hist[row*HP] : &hist[32*HP + row*HP], 1, row, sh);
        }
        __syncthreads();
    }

    // ---------------- exp + masked Z sums (deterministic) ----------------
    unsigned mb1[4] = {0,0,0,0}, mb2[4] = {0,0,0,0};
    unsigned t1r[4], t2r[4];
    float mr[4];
    #pragma unroll
    for (int rs = 0; rs < 4; rs++) {
        int row = gg + 8*rs;
        t1r[rs] = s_p[0][row];
        t2r[rs] = s_p[1][row];
        unsigned um = s_umax[row];
        mr[rs] = (um & 0x80000000u) ? __uint_as_float(um & 0x7FFFFFFFu)
                                    : __uint_as_float(~um);
    }
    float zl1[4] = {0,0,0,0}, zl2[4] = {0,0,0,0};
    #pragma unroll
    for (int c = 0; c < 8; c++)
        #pragma unroll
        for (int mt = 0; mt < 2; mt++)
            #pragma unroll
            for (int nt = 0; nt < 2; nt++)
                #pragma unroll
                for (int e = 0; e < 4; e++) {
                    int rs = (e >> 1) + 2*mt;
                    unsigned u = __float_as_uint(acc[c][mt][nt][e]);
                    float v = (u & 0x80000000u) ? __uint_as_float(u & 0x7FFFFFFFu)
                                                : __uint_as_float(~u);
                    float ev = __expf(v - mr[rs]);
                    acc[c][mt][nt][e] = ev;
                    int idx = c*16 + mt*8 + nt*4 + e;
                    if (u >= t1r[rs]) { zl1[rs] += ev; mb1[idx >> 5] |= (1u << (idx & 31)); }
                    if (u >= t2r[rs]) { zl2[rs] += ev; mb2[idx >> 5] |= (1u << (idx & 31)); }
                }
    #pragma unroll
    for (int rs = 0; rs < 4; rs++) {
        zl1[rs] += __shfl_xor_sync(0xFFFFFFFFu, zl1[rs], 1);
        zl1[rs] += __shfl_xor_sync(0xFFFFFFFFu, zl1[rs], 2);
        zl2[rs] += __shfl_xor_sync(0xFFFFFFFFu, zl2[rs], 1);
        zl2[rs] += __shfl_xor_sync(0xFFFFFFFFu, zl2[rs], 2);
        if (qq == 0) { zp[0][gg + 8*rs][w] = zl1[rs]; zp[1][gg + 8*rs][w] = zl2[rs]; }
    }
    __syncthreads();
    if (tid < 32) {
        float a = 0.f, bsum = 0.f;
        #pragma unroll
        for (int j = 0; j < 8; j++) { a += zp[0][tid][j]; bsum += zp[1][tid][j]; }
        s_z[0][tid] = a; s_z[1][tid] = bsum;
    }
    __syncthreads();

    // ---------------- write W (bf16) ----------------
    float c1r[4], c2r[4];
    #pragma unroll
    for (int rs = 0; rs < 4; rs++) {
        int row = gg + 8*rs;
        c1r[rs] = 0.6f / s_z[0][row];
        c2r[rs] = 0.4f / s_z[1][row];
    }
    __nv_bfloat16* Wb = g_W + (size_t)head * 1024 * 1024 + (size_t)m0 * 1024;
    #pragma unroll
    for (int c = 0; c < 8; c++)
        #pragma unroll
        for (int mt = 0; mt < 2; mt++)
            #pragma unroll
            for (int nt = 0; nt < 2; nt++)
                #pragma unroll
                for (int pr = 0; pr < 2; pr++) {
                    int rs = pr + 2*mt;
                    int row = gg + 8*rs;
                    int col = c*128 + w*16 + nt*8 + 2*qq;
                    int i0 = c*16 + mt*8 + nt*4 + 2*pr;
                    float e0 = acc[c][mt][nt][2*pr];
                    float e1 = acc[c][mt][nt][2*pr + 1];
                    float w0 = e0 * (((mb1[i0 >> 5] >> (i0 & 31)) & 1u) ? c1r[rs] : 0.f)
                             + e0 * (((mb2[i0 >> 5] >> (i0 & 31)) & 1u) ? c2r[rs] : 0.f);
                    int i1 = i0 + 1;
                    float w1 = e1 * (((mb1[i1 >> 5] >> (i1 & 31)) & 1u) ? c1r[rs] : 0.f)
                             + e1 * (((mb2[i1 >> 5] >> (i1 & 31)) & 1u) ? c2r[rs] : 0.f);
                    *(__nv_bfloat162*)&Wb[(size_t)row * 1024 + col] =
                        __halves2bfloat162(__float2bfloat16(w0), __float2bfloat16(w1));
                }
}

// ======================= launch =======================
extern "C" void kernel_launch(void* const* d_in, const int* in_sizes, int n_in,
                              void* d_out, int out_size)
{
    const float* x   = (const float*)d_in[0];
    const float* y   = (const float*)d_in[1];
    const float* c1w = (const float*)d_in[2];
    const float* c1b = (const float*)d_in[3];
    const float* c2w = (const float*)d_in[4];
    const float* c2b = (const float*)d_in[5];
    const float* c3w = (const float*)d_in[6];
    const float* c3b = (const float*)d_in[7];
    const float* lnw = (const float*)d_in[8];
    const float* lnb = (const float*)d_in[9];
    const float* qw  = (const float*)d_in[10];
    const float* kvw = (const float*)d_in[11];
    const float* pw  = (const float*)d_in[12];
    const float* pb  = (const float*)d_in[13];
    const int*   pk1 = (const int*)d_in[14];
    const int*   pk2 = (const int*)d_in[15];
    float* out = (float*)d_out;

    #define SYM(p, g) void* p; cudaGetSymbolAddress(&p, g)
    SYM(x16, g_x16);   SYM(yn16, g_yn16);
    SYM(q16, g_q16);   SYM(kv16, g_kv16);
    SYM(vt16, g_vt16); SYM(W, g_W);
    SYM(at16, g_at16);
    SYM(qw16, g_qw16); SYM(kvw16, g_kvw16); SYM(pw16, g_pw16);
    #undef SYM

    const int SM128 = 2 * (128 + 128) * 72 * 2;   // 73728
    const int SM64  = 2 * (128 + 64)  * 72 * 2;   // 55296
    const int SMSS  = 2 * 32 * HP * 4;            // 69632 (hist; covers GEMM staging too)
    cudaFuncSetAttribute(mma_gemm<128,1>, cudaFuncAttributeMaxDynamicSharedMemorySize, SM128);
    cudaFuncSetAttribute(mma_gemm<128,2>, cudaFuncAttributeMaxDynamicSharedMemorySize, SM128);
    cudaFuncSetAttribute(mma_gemm<64,2>,  cudaFuncAttributeMaxDynamicSharedMemorySize, SM64);
    cudaFuncSetAttribute(score_select_kernel, cudaFuncAttributeMaxDynamicSharedMemorySize, SMSS);

    // 1) conv + LN -> ynorm bf16
    conv_ln_kernel<<<B_*NYk, 256>>>(y, c1w, c1b, c2w, c2b, c3w, c3b, lnw, lnb);

    // 2) bf16 conversions
    cvt_kernel<<<3072, 256>>>(x,  (__nv_bfloat16*)x16,  786432);
    cvt_kernel<<<576,  256>>>(qw, (__nv_bfloat16*)qw16, 147456);
    cvt_kernel<<<1152, 256>>>(kvw,(__nv_bfloat16*)kvw16,294912);
    cvt_kernel<<<576,  256>>>(pw, (__nv_bfloat16*)pw16, 147456);

    // 3) q = x @ q_w^T  -> bf16
    mma_gemm<128,2><<<dim3(6,32,1), 256, SM128>>>(
        (const __nv_bfloat16*)x16, (const __nv_bfloat16*)qw16,
        nullptr, (__nv_bfloat16*)q16, nullptr, nullptr,
        768, 768, 768, 768, 1.0f, 1, 0,0,0,0,0,0);

    // 4) kv = y_norm @ kv_w^T -> bf16
    mma_gemm<128,2><<<dim3(12,32,1), 256, SM128>>>(
        (const __nv_bfloat16*)yn16, (const __nv_bfloat16*)kvw16,
        nullptr, (__nv_bfloat16*)kv16, nullptr, nullptr,
        768, 768, 768, 1536, 1.0f, 1, 0,0,0,0,0,0);

    // 5) V^T
    vtrans_kernel<<<dim3(48,32), 256>>>();

    // 6+7) fused scores + dual top-k + softmax weights -> W bf16
    score_select_kernel<<<dim3(32,48), 256, SMSS>>>(pk1, pk2);

    // 8) attn = W @ V^T -> bf16
    mma_gemm<64,2><<<dim3(1,8,48), 256, SM64>>>(
        (const __nv_bfloat16*)W, (const __nv_bfloat16*)vt16,
        nullptr, (__nv_bfloat16*)at16, nullptr, nullptr,
        1024, 1024, 1024, 768, 1.0f, 12,
        (long long)12*1024*1024, (long long)1024*1024,
        (long long)12*64*1024,   (long long)64*1024,
        (long long)1024*768, 64);

    // 9) out = attn @ proj_w^T + proj_b + x
    mma_gemm<128,1><<<dim3(6,32,1), 256, SM128>>>(
        (const __nv_bfloat16*)at16, (const __nv_bfloat16*)pw16,
        out, nullptr, pb, x,
        768, 768, 768, 768, 1.0f, 1, 0,0,0,0,0,0);
}

// round 7
// speedup vs baseline: 2.4278x; 2.4278x over previous
#include <cuda_runtime.h>
#include <cuda_bf16.h>
#include <cstdint>

#define B_  4
#define NXq 1024
#define NYk 1024
#define C_  768
#define H_  12
#define D_  64

// ======================= scratch (static device globals) =======================
__device__ float g_S[48u*1024u*1024u];                        // fp32 scores
__device__ __align__(16) __nv_bfloat16 g_x16 [B_*NXq*C_];
__device__ __align__(16) __nv_bfloat16 g_yn16[B_*NYk*C_];
__device__ __align__(16) __nv_bfloat16 g_q16 [B_*NXq*C_];
__device__ __align__(16) __nv_bfloat16 g_kv16[B_*NYk*2*C_];
__device__ __align__(16) __nv_bfloat16 g_vt16[48*64*1024];
__device__ __align__(16) __nv_bfloat16 g_W   [48u*1024u*1024u];
__device__ __align__(16) __nv_bfloat16 g_at16[B_*NXq*C_];
__device__ __align__(16) __nv_bfloat16 g_qw16 [C_*C_];
__device__ __align__(16) __nv_bfloat16 g_kvw16[2*C_*C_];
__device__ __align__(16) __nv_bfloat16 g_pw16 [C_*C_];

__device__ __forceinline__ uint32_t smem_u32(const void* p) {
    uint32_t a;
    asm("{ .reg .u64 t; cvta.to.shared.u64 t, %1; cvt.u32.u64 %0, t; }" : "=r"(a) : "l"(p));
    return a;
}
__device__ __forceinline__ void cp16(uint32_t dst, const void* src) {
    asm volatile("cp.async.cg.shared.global [%0], [%1], 16;" :: "r"(dst), "l"(src));
}

// ======================= fused multiscale conv + LayerNorm -> bf16 =======================
__global__ void __launch_bounds__(256) conv_ln_kernel(
    const float* __restrict__ y,
    const float* __restrict__ c1w, const float* __restrict__ c1b,
    const float* __restrict__ c2w, const float* __restrict__ c2b,
    const float* __restrict__ c3w, const float* __restrict__ c3b,
    const float* __restrict__ lnw, const float* __restrict__ lnb)
{
    int row = blockIdx.x;
    int b  = row >> 10;
    int ny = row & 1023;
    const float* yb = y + (size_t)b * NYk * C_;
    int tid = threadIdx.x;

    float vals[3];
    float lsum = 0.f, lsq = 0.f;
    #pragma unroll
    for (int i = 0; i < 3; i++) {
        int c = tid + i * 256;
        float w7[7];
        #pragma unroll
        for (int j = 0; j < 7; j++) w7[j] = c3w[c*7 + j];
        #pragma unroll
        for (int j = 0; j < 5; j++) w7[j+1] += c2w[c*5 + j];
        #pragma unroll
        for (int j = 0; j < 3; j++) w7[j+2] += c1w[c*3 + j];
        float acc = c1b[c] + c2b[c] + c3b[c];
        #pragma unroll
        for (int j = 0; j < 7; j++) {
            int nn = ny + j - 3;
            if (nn >= 0 && nn < NYk) acc += w7[j] * yb[(size_t)nn * C_ + c];
        }
        vals[i] = acc; lsum += acc; lsq += acc * acc;
    }

    __shared__ float s1[256], s2[256];
    s1[tid] = lsum; s2[tid] = lsq;
    __syncthreads();
    for (int s = 128; s > 0; s >>= 1) {
        if (tid < s) { s1[tid] += s1[tid+s]; s2[tid] += s2[tid+s]; }
        __syncthreads();
    }
    float mean = s1[0] * (1.0f / C_);
    float var  = s2[0] * (1.0f / C_) - mean * mean;
    float rstd = rsqrtf(var + 1e-5f);

    size_t base = (size_t)row * C_;
    #pragma unroll
    for (int i = 0; i < 3; i++) {
        int c = tid + i * 256;
        float v = (vals[i] - mean) * rstd * lnw[c] + lnb[c];
        g_yn16[base + c] = __float2bfloat16(v);
    }
}

// ======================= fp32 -> bf16 convert =======================
__global__ void __launch_bounds__(256) cvt_kernel(const float* __restrict__ s,
                                                  __nv_bfloat16* __restrict__ o,
                                                  int n4)
{
    int i = blockIdx.x * 256 + threadIdx.x;
    if (i >= n4) return;
    float4 v = ((const float4*)s)[i];
    __nv_bfloat162* O = (__nv_bfloat162*)o;
    O[2*i]   = __halves2bfloat162(__float2bfloat16(v.x), __float2bfloat16(v.y));
    O[2*i+1] = __halves2bfloat162(__float2bfloat16(v.z), __float2bfloat16(v.w));
}

// ======================= V transpose =======================
__global__ void __launch_bounds__(256) vtrans_kernel()
{
    int z  = blockIdx.x;
    int t0 = blockIdx.y * 32;
    int b = z / 12, h = z - b*12;
    __shared__ __nv_bfloat16 sh[64][33];
    int tid = threadIdx.x;
    #pragma unroll
    for (int i = 0; i < 8; i++) {
        int idx = tid + i*256;
        int tok = idx >> 6, d = idx & 63;
        size_t off = ((size_t)(b*1024 + t0 + tok)) * 1536 + 768 + h*64 + d;
        sh[d][tok] = g_kv16[off];
    }
    __syncthreads();
    #pragma unroll
    for (int i = 0; i < 8; i++) {
        int o = tid + i*256;
        int d = o >> 5, c = o & 31;
        size_t off = (size_t)z * 64 * 1024 + (size_t)d * 1024 + t0 + c;
        g_vt16[off] = sh[d][c];
    }
}

// ======================= HMMA GEMM (R5, proven) =======================
template<int NT, int OUTM>
__global__ void __launch_bounds__(256) mma_gemm(
    const __nv_bfloat16* __restrict__ A, const __nv_bfloat16* __restrict__ B,
    float* __restrict__ Co, __nv_bfloat16* __restrict__ Cb,
    const float* __restrict__ bias, const float* __restrict__ res,
    int K, int lda, int ldb, int ldc, float alpha, int HH,
    long long aO, long long aI, long long bO, long long bI,
    long long cO, long long cI)
{
    constexpr int WM  = (NT == 128) ? 2 : 4;
    constexpr int WN  = 8 / WM;
    constexpr int WTM = 128 / WM;
    constexpr int WTN = NT / WN;
    constexpr int MT  = WTM / 16;
    constexpr int NTT = WTN / 8;
    constexpr int PITCH = 72;
    constexpr int ABYTES = 128 * PITCH * 2;
    constexpr int BBYTES = NT  * PITCH * 2;
    constexpr int STAGE  = ABYTES + BBYTES;

    extern __shared__ __align__(16) char dsm[];
    uint32_t smbase = smem_u32(dsm);

    int tid = threadIdx.x, wid = tid >> 5, lane = tid & 31;
    int wm = wid % WM, wn = wid / WM;

    int z = blockIdx.z, zo = z / HH, zi = z - zo * HH;
    A += zo*aO + zi*aI;
    B += zo*bO + zi*bI;
    long long coff = zo*cO + zi*cI;

    long long m0 = (long long)blockIdx.y * 128;
    long long n0 = (long long)blockIdx.x * NT;

    float acc[MT][NTT][4];
    #pragma unroll
    for (int i = 0; i < MT; i++)
        #pragma unroll
        for (int j = 0; j < NTT; j++)
            #pragma unroll
            for (int r = 0; r < 4; r++) acc[i][j][r] = 0.f;

    int nIter = K >> 6;

    uint32_t a_off = ((uint32_t)(wm*WTM + (lane & 15)) * PITCH + ((lane >> 4) << 3)) * 2;
    uint32_t b_off = ABYTES + ((uint32_t)(wn*WTN + (lane & 7)) * PITCH + (((lane >> 3) & 1) << 3)) * 2;

    auto issue = [&](int t) {
        int k0 = t << 6, s = t & 1;
        uint32_t sa = smbase + s * STAGE;
        uint32_t sb = sa + ABYTES;
        #pragma unroll
        for (int i = 0; i < 4; i++) {
            int ch = tid + (i << 8);
            int r = ch >> 3, c = (ch & 7) << 3;
            cp16(sa + (uint32_t)(r*PITCH + c)*2, A + (m0 + r)*lda + k0 + c);
        }
        #pragma unroll
        for (int i = 0; i < NT/32; i++) {
            int ch = tid + (i << 8);
            int r = ch >> 3, c = (ch & 7) << 3;
            cp16(sb + (uint32_t)(r*PITCH + c)*2, B + (n0 + r)*ldb + k0 + c);
        }
        asm volatile("cp.async.commit_group;");
    };

    issue(0);
    for (int t = 0; t < nIter; t++) {
        if (t + 1 < nIter) {
            issue(t + 1);
            asm volatile("cp.async.wait_group 1;");
        } else {
            asm volatile("cp.async.wait_group 0;");
        }
        __syncthreads();
        uint32_t stg = smbase + (uint32_t)(t & 1) * STAGE;
        uint32_t abase = stg + a_off;
        uint32_t bbase = stg + b_off;

        #pragma unroll
        for (int ks = 0; ks < 4; ks++) {
            uint32_t kb = (uint32_t)ks << 5;
            uint32_t af[MT][4];
            #pragma unroll
            for (int mt = 0; mt < MT; mt++) {
                asm volatile("ldmatrix.sync.aligned.m8n8.x4.shared.b16 {%0,%1,%2,%3}, [%4];"
                    : "=r"(af[mt][0]), "=r"(af[mt][1]), "=r"(af[mt][2]), "=r"(af[mt][3])
                    : "r"(abase + (uint32_t)(mt*16*PITCH*2) + kb));
            }
            uint32_t bf[NTT][2];
            #pragma unroll
            for (int nt = 0; nt < NTT; nt++) {
                asm volatile("ldmatrix.sync.aligned.m8n8.x2.shared.b16 {%0,%1}, [%2];"
                    : "=r"(bf[nt][0]), "=r"(bf[nt][1])
                    : "r"(bbase + (uint32_t)(nt*8*PITCH*2) + kb));
            }
            #pragma unroll
            for (int mt = 0; mt < MT; mt++)
                #pragma unroll
                for (int nt = 0; nt < NTT; nt++) {
                    asm volatile(
                        "mma.sync.aligned.m16n8k16.row.col.f32.bf16.bf16.f32 "
                        "{%0,%1,%2,%3}, {%4,%5,%6,%7}, {%8,%9}, {%0,%1,%2,%3};"
                        : "+f"(acc[mt][nt][0]), "+f"(acc[mt][nt][1]),
                          "+f"(acc[mt][nt][2]), "+f"(acc[mt][nt][3])
                        : "r"(af[mt][0]), "r"(af[mt][1]), "r"(af[mt][2]), "r"(af[mt][3]),
                          "r"(bf[nt][0]), "r"(bf[nt][1]));
                }
        }
        __syncthreads();
    }

    int gg = lane >> 2, qq = lane & 3;
    #pragma unroll
    for (int mt = 0; mt < MT; mt++) {
        long long gm = m0 + wm*WTM + mt*16 + gg;
        #pragma unroll
        for (int nt = 0; nt < NTT; nt++) {
            long long gn = n0 + wn*WTN + nt*8 + 2*qq;
            float v0 = acc[mt][nt][0] * alpha;
            float v1 = acc[mt][nt][1] * alpha;
            float v2 = acc[mt][nt][2] * alpha;
            float v3 = acc[mt][nt][3] * alpha;
            long long gi0 = coff + gm * (long long)ldc + gn;
            long long gi1 = gi0 + 8LL * ldc;
            if (OUTM == 0) {
                *(float2*)&Co[gi0] = make_float2(v0, v1);
                *(float2*)&Co[gi1] = make_float2(v2, v3);
            } else if (OUTM == 1) {
                float b0 = bias[gn], b1 = bias[gn + 1];
                float2 r0 = *(const float2*)&res[gi0];
                float2 r1 = *(const float2*)&res[gi1];
                *(float2*)&Co[gi0] = make_float2(v0 + b0 + r0.x, v1 + b1 + r0.y);
                *(float2*)&Co[gi1] = make_float2(v2 + b0 + r1.x, v3 + b1 + r1.y);
            } else {
                *(__nv_bfloat162*)&Cb[gi0] =
                    __halves2bfloat162(__float2bfloat16(v0), __float2bfloat16(v1));
                *(__nv_bfloat162*)&Cb[gi1] =
                    __halves2bfloat162(__float2bfloat16(v2), __float2bfloat16(v3));
            }
        }
    }
}

// ======================= warp-per-row dual top-k select -> W (bf16) =======================
// One warp owns one row of S. No __syncthreads. Keys in registers (u-space),
// per-warp 2x256-bin smem histogram, shfl suffix scans, ballot broadcast.
__global__ void __launch_bounds__(256) select_kernel(const int* __restrict__ pk1,
                                                     const int* __restrict__ pk2)
{
    __shared__ unsigned hist[8][512];

    int tid = threadIdx.x, lane = tid & 31, wid = tid >> 5;
    long long row = (long long)blockIdx.x * 8 + wid;
    const float* Srow = g_S + row * 1024;

    // load 32 keys per lane, coalesced: element j*128 + lane*4 .. +3
    unsigned u[32];
    unsigned umax = 0u;
    #pragma unroll
    for (int j = 0; j < 8; j++) {
        float4 f = *(const float4*)(Srow + j*128 + lane*4);
        float vv[4] = {f.x, f.y, f.z, f.w};
        #pragma unroll
        for (int e = 0; e < 4; e++) {
            unsigned b = __float_as_uint(vv[e]);
            unsigned k = (b & 0x80000000u) ? ~b : (b | 0x80000000u);
            u[j*4 + e] = k;
            umax = (k > umax) ? k : umax;
        }
    }
    #pragma unroll
    for (int d = 16; d > 0; d >>= 1) {
        unsigned o = __shfl_xor_sync(0xFFFFFFFFu, umax, d);
        umax = (o > umax) ? o : umax;
    }
    float m = (umax & 0x80000000u) ? __uint_as_float(umax & 0x7FFFFFFFu)
                                   : __uint_as_float(~umax);

    int k1 = *pk1, k2 = *pk2;
    unsigned* h0 = hist[wid];
    unsigned* h1 = hist[wid] + 256;

    // warp scan of a 256-bin histogram; returns updated (prefix, kk) lane-uniform
    auto scan1 = [&](const unsigned* h, unsigned pfx, int kk, int sh,
                     unsigned& pout, int& kout) {
        unsigned h8[8];
        #pragma unroll
        for (int i = 0; i < 8; i++) h8[i] = h[lane*8 + i];
        unsigned tot = 0;
        #pragma unroll
        for (int i = 0; i < 8; i++) tot += h8[i];
        unsigned s = tot;
        #pragma unroll
        for (int d = 1; d < 32; d <<= 1) {
            unsigned t = __shfl_down_sync(0xFFFFFFFFu, s, d);
            if (lane + d < 32) s += t;
        }
        unsigned run = s - tot;        // counts in bins above this lane's range
        unsigned myp = 0u; int myk = 0; bool found = false;
        #pragma unroll
        for (int i = 7; i >= 0; i--) {
            unsigned cn = run;
            run += h8[i];
            if (!found && run >= (unsigned)kk && cn < (unsigned)kk) {
                found = true;
                myp = pfx | ((unsigned)(lane*8 + i) << sh);
                myk = kk - (int)cn;
            }
        }
        unsigned ball = __ballot_sync(0xFFFFFFFFu, found);
        int src = __ffs(ball) - 1;
        pout = __shfl_sync(0xFFFFFFFFu, myp, src);
        kout = __shfl_sync(0xFFFFFFFFu, myk, src);
    };

    // ---- level 3: unfiltered, one hist serves both thresholds ----
    #pragma unroll
    for (int i = 0; i < 8; i++) h0[lane*8 + i] = 0u;
    __syncwarp();
    #pragma unroll
    for (int j = 0; j < 32; j++) atomicAdd(&h0[u[j] >> 24], 1u);
    __syncwarp();
    unsigned p1, p2; int kk1, kk2;
    scan1(h0, 0u, k1, 24, p1, kk1);
    scan1(h0, 0u, k2, 24, p2, kk2);

    // ---- levels 2..0 ----
    #pragma unroll
    for (int lev = 2; lev >= 0; lev--) {
        int sh = lev * 8;
        unsigned himask = 0xFFFFFFFFu << (sh + 8);
        bool same = (p1 == p2);
        __syncwarp();
        #pragma unroll
        for (int i = 0; i < 16; i++) hist[wid][lane*16 + i] = 0u;
        __syncwarp();
        #pragma unroll
        for (int j = 0; j < 32; j++) {
            unsigned uu = u[j];
            if (((uu ^ p1) & himask) == 0u) atomicAdd(&h0[(uu >> sh) & 255u], 1u);
            if (!same && ((uu ^ p2) & himask) == 0u) atomicAdd(&h1[(uu >> sh) & 255u], 1u);
        }
        __syncwarp();
        unsigned p1o = p1, p2o = p2;
        scan1(h0, p1o, kk1, sh, p1, kk1);
        scan1(same ? h0 : h1, p2o, kk2, sh, p2, kk2);
    }

    // ---- masked Z sums (deterministic lane order) ----
    float z1 = 0.f, z2 = 0.f;
    #pragma unroll
    for (int j = 0; j < 32; j++) {
        unsigned uu = u[j];
        float v = (uu & 0x80000000u) ? __uint_as_float(uu & 0x7FFFFFFFu)
                                     : __uint_as_float(~uu);
        float e = __expf(v - m);
        if (uu >= p1) z1 += e;
        if (uu >= p2) z2 += e;
    }
    #pragma unroll
    for (int d = 16; d > 0; d >>= 1) {
        z1 += __shfl_xor_sync(0xFFFFFFFFu, z1, d);
        z2 += __shfl_xor_sync(0xFFFFFFFFu, z2, d);
    }
    float c1 = 0.6f / z1;
    float c2 = 0.4f / z2;

    // ---- write W ----
    __nv_bfloat16* Wrow = g_W + row * 1024;
    #pragma unroll
    for (int j = 0; j < 8; j++) {
        __nv_bfloat16 o4[4];
        #pragma unroll
        for (int e = 0; e < 4; e++) {
            unsigned uu = u[j*4 + e];
            float v = (uu & 0x80000000u) ? __uint_as_float(uu & 0x7FFFFFFFu)
                                         : __uint_as_float(~uu);
            float ev = __expf(v - m);
            float w = ev * ((uu >= p1) ? c1 : 0.f) + ev * ((uu >= p2) ? c2 : 0.f);
            o4[e] = __float2bfloat16(w);
        }
        *(uint2*)&Wrow[j*128 + lane*4] = *(uint2*)o4;
    }
}

// ======================= launch =======================
extern "C" void kernel_launch(void* const* d_in, const int* in_sizes, int n_in,
                              void* d_out, int out_size)
{
    const float* x   = (const float*)d_in[0];
    const float* y   = (const float*)d_in[1];
    const float* c1w = (const float*)d_in[2];
    const float* c1b = (const float*)d_in[3];
    const float* c2w = (const float*)d_in[4];
    const float* c2b = (const float*)d_in[5];
    const float* c3w = (const float*)d_in[6];
    const float* c3b = (const float*)d_in[7];
    const float* lnw = (const float*)d_in[8];
    const float* lnb = (const float*)d_in[9];
    const float* qw  = (const float*)d_in[10];
    const float* kvw = (const float*)d_in[11];
    const float* pw  = (const float*)d_in[12];
    const float* pb  = (const float*)d_in[13];
    const int*   pk1 = (const int*)d_in[14];
    const int*   pk2 = (const int*)d_in[15];
    float* out = (float*)d_out;

    #define SYM(p, g) void* p; cudaGetSymbolAddress(&p, g)
    SYM(S, g_S);
    SYM(x16, g_x16);   SYM(yn16, g_yn16);
    SYM(q16, g_q16);   SYM(kv16, g_kv16);
    SYM(vt16, g_vt16); SYM(W, g_W);
    SYM(at16, g_at16);
    SYM(qw16, g_qw16); SYM(kvw16, g_kvw16); SYM(pw16, g_pw16);
    #undef SYM

    const int SM128 = 2 * (128 + 128) * 72 * 2;   // 73728
    const int SM64  = 2 * (128 + 64)  * 72 * 2;   // 55296
    cudaFuncSetAttribute(mma_gemm<128,0>, cudaFuncAttributeMaxDynamicSharedMemorySize, SM128);
    cudaFuncSetAttribute(mma_gemm<128,1>, cudaFuncAttributeMaxDynamicSharedMemorySize, SM128);
    cudaFuncSetAttribute(mma_gemm<128,2>, cudaFuncAttributeMaxDynamicSharedMemorySize, SM128);
    cudaFuncSetAttribute(mma_gemm<64,2>,  cudaFuncAttributeMaxDynamicSharedMemorySize, SM64);

    // 1) conv + LN -> ynorm bf16
    conv_ln_kernel<<<B_*NYk, 256>>>(y, c1w, c1b, c2w, c2b, c3w, c3b, lnw, lnb);

    // 2) bf16 conversions
    cvt_kernel<<<3072, 256>>>(x,  (__nv_bfloat16*)x16,  786432);
    cvt_kernel<<<576,  256>>>(qw, (__nv_bfloat16*)qw16, 147456);
    cvt_kernel<<<1152, 256>>>(kvw,(__nv_bfloat16*)kvw16,294912);
    cvt_kernel<<<576,  256>>>(pw, (__nv_bfloat16*)pw16, 147456);

    // 3) q = x @ q_w^T  -> bf16
    mma_gemm<128,2><<<dim3(6,32,1), 256, SM128>>>(
        (const __nv_bfloat16*)x16, (const __nv_bfloat16*)qw16,
        nullptr, (__nv_bfloat16*)q16, nullptr, nullptr,
        768, 768, 768, 768, 1.0f, 1, 0,0,0,0,0,0);

    // 4) kv = y_norm @ kv_w^T -> bf16
    mma_gemm<128,2><<<dim3(12,32,1), 256, SM128>>>(
        (const __nv_bfloat16*)yn16, (const __nv_bfloat16*)kvw16,
        nullptr, (__nv_bfloat16*)kv16, nullptr, nullptr,
        768, 768, 768, 1536, 1.0f, 1, 0,0,0,0,0,0);

    // 5) V^T
    vtrans_kernel<<<dim3(48,32), 256>>>();

    // 6) scores S = (q @ K^T) * D^-0.5  (48 heads) -> fp32
    mma_gemm<128,0><<<dim3(8,8,48), 256, SM128>>>(
        (const __nv_bfloat16*)q16, (const __nv_bfloat16*)kv16,
        (float*)S, nullptr, nullptr, nullptr,
        64, 768, 1536, 1024, 0.125f, 12,
        (long long)1024*768, 64,
        (long long)1024*1536, 64,
        (long long)12*1024*1024, (long long)1024*1024);

    // 7) dual top-k -> combined weights W (bf16), warp-per-row
    select_kernel<<<48*1024/8, 256>>>(pk1, pk2);

    // 8) attn = W @ V^T -> bf16
    mma_gemm<64,2><<<dim3(1,8,48), 256, SM64>>>(
        (const __nv_bfloat16*)W, (const __nv_bfloat16*)vt16,
        nullptr, (__nv_bfloat16*)at16, nullptr, nullptr,
        1024, 1024, 1024, 768, 1.0f, 12,
        (long long)12*1024*1024, (long long)1024*1024,
        (long long)12*64*1024,   (long long)64*1024,
        (long long)1024*768, 64);

    // 9) out = attn @ proj_w^T + proj_b + x
    mma_gemm<128,1><<<dim3(6,32,1), 256, SM128>>>(
        (const __nv_bfloat16*)at16, (const __nv_bfloat16*)pw16,
        out, nullptr, pb, x,
        768, 768, 768, 768, 1.0f, 1, 0,0,0,0,0,0);
}